// round 10
// baseline (speedup 1.0000x reference)
#include <cuda_runtime.h>
#include <math_constants.h>

// Problem shapes (fixed by the dataset instance)
#define NVARS_MAX 2000000
#define N0_MAX    4000000
#define N1_MAX    2000000
#define N2_MAX    1000000

// Scratch intermediates (no allocation allowed). 256B-aligned for bulk stores.
__device__ __align__(256) float g_x [2 + 2 * NVARS_MAX];   // encoded input, 16 MB
__device__ __align__(256) float g_b0[N0_MAX];              // layer0 out,   16 MB
__device__ __align__(256) float g_b1[N1_MAX];              // layer1 out,    8 MB
__device__ __align__(256) float g_b2[N2_MAX];              // layer2 out,    4 MB

#define NTHR 256
#define TILE 1024
#define OPT  (TILE / NTHR)     // outputs per thread per tile = 4
#define NBLK 592               // 148 SMs x 4 resident blocks

// ---------------------------------------------------------------------------
// PTX helpers: 1D bulk async copies (TMA/bulk engine — bypasses the per-SM
// LDG/L1tex sector queue, which is the binding resource for this workload).
// ---------------------------------------------------------------------------
__device__ __forceinline__ unsigned smem_u32(const void* p) {
    return (unsigned)__cvta_generic_to_shared(p);
}

__device__ __forceinline__ void mbar_init(unsigned mbar, unsigned count) {
    asm volatile("mbarrier.init.shared.b64 [%0], %1;" :: "r"(mbar), "r"(count) : "memory");
}
__device__ __forceinline__ void mbar_expect_tx(unsigned mbar, unsigned bytes) {
    asm volatile("mbarrier.arrive.expect_tx.shared.b64 _, [%0], %1;"
                 :: "r"(mbar), "r"(bytes) : "memory");
}
__device__ __forceinline__ void mbar_wait(unsigned mbar, int phase) {
    asm volatile(
        "{\n\t.reg .pred P;\n\t"
        "W%=:\n\t"
        "mbarrier.try_wait.parity.acquire.cta.shared::cta.b64 P, [%0], %1;\n\t"
        "@!P bra W%=;\n\t}"
        :: "r"(mbar), "r"(phase) : "memory");
}
__device__ __forceinline__ void bulk_g2s(unsigned dst_smem, const void* src_gmem,
                                         unsigned bytes, unsigned mbar) {
    asm volatile(
        "cp.async.bulk.shared::cta.global.mbarrier::complete_tx::bytes [%0], [%1], %2, [%3];"
        :: "r"(dst_smem), "l"(src_gmem), "r"(bytes), "r"(mbar) : "memory");
}
__device__ __forceinline__ void bulk_s2g(void* dst_gmem, unsigned src_smem, unsigned bytes) {
    asm volatile("cp.async.bulk.global.shared::cta.bulk_group [%0], [%1], %2;"
                 :: "l"(dst_gmem), "r"(src_smem), "r"(bytes) : "memory");
}
__device__ __forceinline__ void bulk_commit() {
    asm volatile("cp.async.bulk.commit_group;" ::: "memory");
}
template <int N>
__device__ __forceinline__ void bulk_wait_group() {
    asm volatile("cp.async.bulk.wait_group %0;" :: "n"(N) : "memory");
}
__device__ __forceinline__ void fence_proxy_async_shared() {
    asm volatile("fence.proxy.async.shared::cta;" ::: "memory");
}

// ---------------------------------------------------------------------------
// Encode: x[0] = -inf, x[1] = 0, x[2+2i] = w[i], x[3+2i] = log1mexp(w[i])
// ---------------------------------------------------------------------------
__global__ void encode_kernel(const float* __restrict__ w, float* __restrict__ x, int n)
{
    int i = blockIdx.x * blockDim.x + threadIdx.x;
    if (i >= n) return;
    float p = w[i];
    float neg;
    if (p > -0.69314718056f) {
        neg = __logf(-expm1f(p));
    } else {
        neg = log1pf(-__expf(p));
    }
    reinterpret_cast<float2*>(x + 2)[i] = make_float2(p, neg);
    if (i == 0) {
        x[0] = -CUDART_INF_F;
        x[1] = 0.0f;
    }
}

// ---------------------------------------------------------------------------
// Fused layer kernel (IS_LSE selects sum vs log-sum-exp semantics).
// Persistent blocks; double-buffered ptr tiles via cp.async.bulk (off the
// LDG queue); gathers via __ldcg (L1 bypass, L2-resident data); result tiles
// bulk-stored. Tail (n % TILE) done by block 0 with plain guarded LDG/STG.
// ---------------------------------------------------------------------------
template<bool IS_LSE>
__global__ void __launch_bounds__(NTHR)
layer_kernel(const float* __restrict__ x, const int4* __restrict__ ptrs,
             float* __restrict__ out, int n)
{
    __shared__ __align__(16) int4  sptr[2][TILE];   // 2 x 16 KB
    __shared__ __align__(16) float sout[2][TILE];   // 2 x  4 KB
    __shared__ __align__(8)  unsigned long long mbar_store[2];

    const int tid   = threadIdx.x;
    const int nfull = n / TILE;

    unsigned mb[2] = { smem_u32(&mbar_store[0]), smem_u32(&mbar_store[1]) };
    if (tid == 0) {
        mbar_init(mb[0], 1);
        mbar_init(mb[1], 1);
    }
    __syncthreads();

    int ph[2] = {0, 0};

    // prologue: prefetch first tile
    const int t0 = blockIdx.x;
    if (tid == 0 && t0 < nfull) {
        mbar_expect_tx(mb[0], TILE * 16);
        bulk_g2s(smem_u32(sptr[0]), ptrs + (size_t)t0 * TILE, TILE * 16, mb[0]);
    }

    int li = 0;
    for (int t = t0; t < nfull; t += gridDim.x, li++) {
        const int buf = li & 1;

        // prefetch next tile into the other buffer (free since last iteration)
        const int tn = t + gridDim.x;
        if (tid == 0 && tn < nfull) {
            mbar_expect_tx(mb[buf ^ 1], TILE * 16);
            bulk_g2s(smem_u32(sptr[buf ^ 1]), ptrs + (size_t)tn * TILE, TILE * 16, mb[buf ^ 1]);
        }

        mbar_wait(mb[buf], ph[buf]);
        ph[buf] ^= 1;

        int4 p[OPT];
        #pragma unroll
        for (int k = 0; k < OPT; k++) p[k] = sptr[buf][tid + k * NTHR];

        float va[OPT], vb[OPT], vc[OPT], vd[OPT];
        #pragma unroll
        for (int k = 0; k < OPT; k++) {
            va[k] = __ldcg(x + p[k].x);
            vb[k] = __ldcg(x + p[k].y);
            vc[k] = __ldcg(x + p[k].z);
            vd[k] = __ldcg(x + p[k].w);
        }

        #pragma unroll
        for (int k = 0; k < OPT; k++) {
            float r;
            if (IS_LSE) {
                float m = fmaxf(fmaxf(va[k], vb[k]), fmaxf(vc[k], vd[k]));
                if (m == -CUDART_INF_F) {
                    r = -CUDART_INF_F;
                } else {
                    float s = __expf(va[k] - m) + __expf(vb[k] - m)
                            + __expf(vc[k] - m) + __expf(vd[k] - m) + 1e-15f;
                    r = __logf(s) + m;
                }
            } else {
                r = (va[k] + vb[k]) + (vc[k] + vd[k]);
            }
            sout[buf][tid + k * NTHR] = r;
        }

        __syncthreads();   // sout[buf] complete; sptr[buf] free for refill
        if (tid == 0) {
            fence_proxy_async_shared();
            bulk_s2g(out + (size_t)t * TILE, smem_u32(sout[buf]), TILE * 4);
            bulk_commit();
            bulk_wait_group<1>();   // store from 2 tiles ago done -> sout reuse safe
        }
        __syncthreads();
    }

    // tail: n % TILE outputs, block 0, plain guarded path
    if (blockIdx.x == 0) {
        for (int j = nfull * TILE + tid; j < n; j += NTHR) {
            int4 p = ptrs[j];
            float a = __ldcg(x + p.x);
            float b = __ldcg(x + p.y);
            float c = __ldcg(x + p.z);
            float d = __ldcg(x + p.w);
            float r;
            if (IS_LSE) {
                float m = fmaxf(fmaxf(a, b), fmaxf(c, d));
                if (m == -CUDART_INF_F) {
                    r = -CUDART_INF_F;
                } else {
                    float s = __expf(a - m) + __expf(b - m)
                            + __expf(c - m) + __expf(d - m) + 1e-15f;
                    r = __logf(s) + m;
                }
            } else {
                r = (a + b) + (c + d);
            }
            out[j] = r;
        }
    }

    if (tid == 0) bulk_wait_group<0>();   // all bulk stores done before exit
}

extern "C" void kernel_launch(void* const* d_in, const int* in_sizes, int n_in,
                              void* d_out, int out_size)
{
    // metadata order (setup_inputs dict order):
    //   0:weights 1:ptrs0 2:csr0 3:n0 4:ptrs1 5:csr1 6:n1
    //   7:ptrs2 8:csr2 9:n2 10:ptrs3 11:csr3 12:n3
    // Fallback if scalars are not passed: 1:ptrs0 3:ptrs1 5:ptrs2 7:ptrs3
    int i0, i1, i2, i3;
    if (n_in >= 13) { i0 = 1; i1 = 4; i2 = 7; i3 = 10; }
    else            { i0 = 1; i1 = 3; i2 = 5; i3 = 7;  }

    const float* w  = (const float*)d_in[0];
    const int4*  p0 = (const int4*) d_in[i0];
    const int4*  p1 = (const int4*) d_in[i1];
    const int4*  p2 = (const int4*) d_in[i2];
    const int4*  p3 = (const int4*) d_in[i3];

    int n_vars = in_sizes[0];
    int n0 = in_sizes[i0] / 4;
    int n1 = in_sizes[i1] / 4;
    int n2 = in_sizes[i2] / 4;
    int n3 = in_sizes[i3] / 4;   // == out_size

    float *x, *b0, *b1, *b2;
    cudaGetSymbolAddress((void**)&x,  g_x);
    cudaGetSymbolAddress((void**)&b0, g_b0);
    cudaGetSymbolAddress((void**)&b1, g_b1);
    cudaGetSymbolAddress((void**)&b2, g_b2);

    encode_kernel       <<<(n_vars + NTHR - 1) / NTHR, NTHR>>>(w, x, n_vars);
    layer_kernel<false> <<<NBLK, NTHR>>>(x,  p0, b0, n0);
    layer_kernel<true>  <<<NBLK, NTHR>>>(b0, p1, b1, n1);
    layer_kernel<false> <<<NBLK, NTHR>>>(b1, p2, b2, n2);
    layer_kernel<true>  <<<NBLK, NTHR>>>(b2, p3, (float*)d_out, n3);
}

// round 11
// speedup vs baseline: 1.7462x; 1.7462x over previous
#include <cuda_runtime.h>
#include <math_constants.h>

// Problem shapes (fixed by the dataset instance)
#define NVARS_MAX 2000000
#define N0_MAX    4000000
#define N1_MAX    2000000
#define N2_MAX    1000000

#define NTHR 256
#define UB   4            // outputs batched per thread per loop iteration

// Scratch intermediates (no allocation allowed).
__device__ float g_x [2 + 2 * NVARS_MAX];   // encoded input, 16 MB
__device__ float g_b0[N0_MAX];              // layer0 out,   16 MB
__device__ float g_b1[N1_MAX];              // layer1 out,    8 MB
__device__ float g_b2[N2_MAX];              // layer2 out,    4 MB

// Software grid barrier state. Phase is monotonically increasing -> safe
// across graph replays (count always returns to 0; phase just keeps rising).
__device__ unsigned g_count = 0;
__device__ unsigned g_phase = 0;

__device__ __forceinline__ void grid_barrier()
{
    __threadfence();               // my stores visible GPU-wide before arrival
    __syncthreads();
    if (threadIdx.x == 0) {
        volatile unsigned* vp = &g_phase;
        unsigned ph = *vp;         // phase == current barrier index (see proof in notes)
        if (atomicAdd(&g_count, 1u) == gridDim.x - 1) {
            g_count = 0;           // reset BEFORE release
            __threadfence();
            atomicAdd(&g_phase, 1u);   // release
        } else {
            while ((int)(*vp - ph) <= 0) { __nanosleep(64); }
        }
        __threadfence();           // acquire
    }
    __syncthreads();
}

// ---------------------------------------------------------------------------
// One circuit layer. IS_LSE=false: product node (segment sum of 4 logs).
// IS_LSE=true: sum node (stable 4-way log-sum-exp + 1e-15).
// Free-running persistent grid-stride, UB outputs batched per iteration so
// 4*UB independent gathers are in flight per thread (R5/R7-proven shape).
// ---------------------------------------------------------------------------
template<bool IS_LSE>
__device__ __forceinline__ void layer(const float* __restrict__ x,
                                      const int4*  __restrict__ ptrs,
                                      float*       __restrict__ out,
                                      int n, int tid0, int S)
{
    for (int base = tid0; base < n; base += UB * S) {
        int4 p[UB];
        #pragma unroll
        for (int k = 0; k < UB; k++) {
            int j = base + k * S;
            if (j < n) p[k] = __ldg(ptrs + j);
        }
        float va[UB], vb[UB], vc[UB], vd[UB];
        #pragma unroll
        for (int k = 0; k < UB; k++) {
            int j = base + k * S;
            if (j < n) {
                va[k] = __ldg(x + p[k].x);
                vb[k] = __ldg(x + p[k].y);
                vc[k] = __ldg(x + p[k].z);
                vd[k] = __ldg(x + p[k].w);
            }
        }
        #pragma unroll
        for (int k = 0; k < UB; k++) {
            int j = base + k * S;
            if (j < n) {
                float r;
                if (IS_LSE) {
                    float m = fmaxf(fmaxf(va[k], vb[k]), fmaxf(vc[k], vd[k]));
                    if (m == -CUDART_INF_F) {
                        r = -CUDART_INF_F;   // all four -inf (matches reference)
                    } else {
                        float s = __expf(va[k] - m) + __expf(vb[k] - m)
                                + __expf(vc[k] - m) + __expf(vd[k] - m) + 1e-15f;
                        r = __logf(s) + m;
                    }
                } else {
                    r = (va[k] + vb[k]) + (vc[k] + vd[k]);
                }
                out[j] = r;
            }
        }
    }
}

// ---------------------------------------------------------------------------
// Fully fused persistent kernel: encode -> L0(sum) -> L1(lse) -> L2(sum) ->
// L3(lse), grid barriers between stages. Launched with exactly 4 blocks/SM
// (__launch_bounds__ guarantees residency; no smem, regs <= 64) so the
// software barrier cannot deadlock.
// ---------------------------------------------------------------------------
__global__ void __launch_bounds__(NTHR, 4)
fused_kernel(const float* __restrict__ w,
             const int4* __restrict__ p0, const int4* __restrict__ p1,
             const int4* __restrict__ p2, const int4* __restrict__ p3,
             float* __restrict__ dout,
             int n_vars, int n0, int n1, int n2, int n3)
{
    const int S    = gridDim.x * blockDim.x;
    const int tid0 = blockIdx.x * blockDim.x + threadIdx.x;

    // Stage -1: encode.  x[0]=-inf, x[1]=0, x[2+2i]=w[i], x[3+2i]=log1mexp(w[i])
    for (int i = tid0; i < n_vars; i += S) {
        float p = w[i];
        float neg;
        if (p > -0.69314718056f) {
            neg = __logf(-expm1f(p));
        } else {
            neg = log1pf(-__expf(p));
        }
        reinterpret_cast<float2*>(g_x + 2)[i] = make_float2(p, neg);
    }
    if (tid0 == 0) { g_x[0] = -CUDART_INF_F; g_x[1] = 0.0f; }

    grid_barrier();
    layer<false>(g_x,  p0, g_b0, n0, tid0, S);
    grid_barrier();
    layer<true >(g_b0, p1, g_b1, n1, tid0, S);
    grid_barrier();
    layer<false>(g_b1, p2, g_b2, n2, tid0, S);
    grid_barrier();
    layer<true >(g_b2, p3, dout, n3, tid0, S);
}

extern "C" void kernel_launch(void* const* d_in, const int* in_sizes, int n_in,
                              void* d_out, int out_size)
{
    // metadata order (setup_inputs dict order):
    //   0:weights 1:ptrs0 2:csr0 3:n0 4:ptrs1 5:csr1 6:n1
    //   7:ptrs2 8:csr2 9:n2 10:ptrs3 11:csr3 12:n3
    // Fallback if scalars are not passed: 1:ptrs0 3:ptrs1 5:ptrs2 7:ptrs3
    int i0, i1, i2, i3;
    if (n_in >= 13) { i0 = 1; i1 = 4; i2 = 7; i3 = 10; }
    else            { i0 = 1; i1 = 3; i2 = 5; i3 = 7;  }

    const float* w  = (const float*)d_in[0];
    const int4*  p0 = (const int4*) d_in[i0];
    const int4*  p1 = (const int4*) d_in[i1];
    const int4*  p2 = (const int4*) d_in[i2];
    const int4*  p3 = (const int4*) d_in[i3];

    int n_vars = in_sizes[0];
    int n0 = in_sizes[i0] / 4;
    int n1 = in_sizes[i1] / 4;
    int n2 = in_sizes[i2] / 4;
    int n3 = in_sizes[i3] / 4;   // == out_size

    // Host code runs only at capture time; query the real SM count so the
    // persistent grid is exactly 4 blocks per SM (148 on B300, 152 on GB300).
    int nsm = 148;
    cudaDeviceGetAttribute(&nsm, cudaDevAttrMultiProcessorCount, 0);
    int nblk = 4 * nsm;

    fused_kernel<<<nblk, NTHR>>>(w, p0, p1, p2, p3, (float*)d_out,
                                 n_vars, n0, n1, n2, n3);
}

// round 13
// speedup vs baseline: 1.7697x; 1.0135x over previous
#include <cuda_runtime.h>
#include <math_constants.h>

// Problem shapes (fixed by the dataset instance)
#define NVARS_MAX 2000000
#define N0_MAX    4000000
#define N1_MAX    2000000
#define N2_MAX    1000000

#define NTHR 256
#define UB   2            // outputs batched per thread per loop iteration
#define BLKS_PER_SM 6     // 48 warps/SM; launch_bounds forces regs <= 42

// Scratch intermediates (no allocation allowed).
__device__ float g_x [2 + 2 * NVARS_MAX];   // encoded input, 16 MB
__device__ float g_b0[N0_MAX];              // layer0 out,   16 MB
__device__ float g_b1[N1_MAX];              // layer1 out,    8 MB
__device__ float g_b2[N2_MAX];              // layer2 out,    4 MB

// Software grid barrier. Phase is monotonically increasing -> replay-safe
// (count returns to 0 each barrier; phase keeps rising across replays).
__device__ unsigned g_count = 0;
__device__ unsigned g_phase = 0;

__device__ __forceinline__ void grid_barrier()
{
    __threadfence();               // my stores visible GPU-wide before arrival
    __syncthreads();
    if (threadIdx.x == 0) {
        volatile unsigned* vp = &g_phase;
        unsigned ph = *vp;
        if (atomicAdd(&g_count, 1u) == gridDim.x - 1) {
            g_count = 0;           // reset BEFORE release
            __threadfence();
            atomicAdd(&g_phase, 1u);   // release
        } else {
            while ((int)(*vp - ph) <= 0) { __nanosleep(64); }
        }
        __threadfence();           // acquire
    }
    __syncthreads();
}

// ---------------------------------------------------------------------------
// One circuit layer. IS_LSE=false: product node (sum of 4 gathered logs).
// IS_LSE=true: sum node (stable 4-way log-sum-exp + 1e-15).
// Free-running grid-stride; UB outputs batched -> 4*UB+UB loads in flight
// per thread, 48 warps/SM feeding the l1tex queue continuously.
// ---------------------------------------------------------------------------
template<bool IS_LSE>
__device__ __forceinline__ void layer(const float* __restrict__ x,
                                      const int4*  __restrict__ ptrs,
                                      float*       __restrict__ out,
                                      int n, int tid0, int S)
{
    for (int base = tid0; base < n; base += UB * S) {
        int4 p[UB];
        #pragma unroll
        for (int k = 0; k < UB; k++) {
            int j = base + k * S;
            if (j < n) p[k] = __ldg(ptrs + j);
        }
        float va[UB], vb[UB], vc[UB], vd[UB];
        #pragma unroll
        for (int k = 0; k < UB; k++) {
            int j = base + k * S;
            if (j < n) {
                va[k] = __ldg(x + p[k].x);
                vb[k] = __ldg(x + p[k].y);
                vc[k] = __ldg(x + p[k].z);
                vd[k] = __ldg(x + p[k].w);
            }
        }
        #pragma unroll
        for (int k = 0; k < UB; k++) {
            int j = base + k * S;
            if (j < n) {
                float r;
                if (IS_LSE) {
                    float m = fmaxf(fmaxf(va[k], vb[k]), fmaxf(vc[k], vd[k]));
                    if (m == -CUDART_INF_F) {
                        r = -CUDART_INF_F;   // all four -inf (matches reference)
                    } else {
                        float s = __expf(va[k] - m) + __expf(vb[k] - m)
                                + __expf(vc[k] - m) + __expf(vd[k] - m) + 1e-15f;
                        r = __logf(s) + m;
                    }
                } else {
                    r = (va[k] + vb[k]) + (vc[k] + vd[k]);
                }
                out[j] = r;
            }
        }
    }
}

// ---------------------------------------------------------------------------
// Fully fused persistent kernel: encode -> L0(sum) -> L1(lse) -> L2(sum) ->
// L3(lse) with grid barriers. 6 blocks/SM, no smem, regs capped by
// __launch_bounds__ -> full residency guaranteed -> barrier cannot deadlock.
// ---------------------------------------------------------------------------
__global__ void __launch_bounds__(NTHR, BLKS_PER_SM)
fused_kernel(const float* __restrict__ w,
             const int4* __restrict__ p0, const int4* __restrict__ p1,
             const int4* __restrict__ p2, const int4* __restrict__ p3,
             float* __restrict__ dout,
             int n_vars, int n0, int n1, int n2, int n3)
{
    const int S    = gridDim.x * blockDim.x;
    const int tid0 = blockIdx.x * blockDim.x + threadIdx.x;

    // Encode: x[0]=-inf, x[1]=0, x[2+2i]=w[i], x[3+2i]=log1mexp(w[i])
    for (int i = tid0; i < n_vars; i += S) {
        float p = w[i];
        float neg;
        if (p > -0.69314718056f) {
            neg = __logf(-expm1f(p));
        } else {
            neg = log1pf(-__expf(p));
        }
        reinterpret_cast<float2*>(g_x + 2)[i] = make_float2(p, neg);
    }
    if (tid0 == 0) { g_x[0] = -CUDART_INF_F; g_x[1] = 0.0f; }

    grid_barrier();
    layer<false>(g_x,  p0, g_b0, n0, tid0, S);
    grid_barrier();
    layer<true >(g_b0, p1, g_b1, n1, tid0, S);
    grid_barrier();
    layer<false>(g_b1, p2, g_b2, n2, tid0, S);
    grid_barrier();
    layer<true >(g_b2, p3, dout, n3, tid0, S);
}

extern "C" void kernel_launch(void* const* d_in, const int* in_sizes, int n_in,
                              void* d_out, int out_size)
{
    // metadata order (setup_inputs dict order):
    //   0:weights 1:ptrs0 2:csr0 3:n0 4:ptrs1 5:csr1 6:n1
    //   7:ptrs2 8:csr2 9:n2 10:ptrs3 11:csr3 12:n3
    // Fallback if scalars are not passed: 1:ptrs0 3:ptrs1 5:ptrs2 7:ptrs3
    int i0, i1, i2, i3;
    if (n_in >= 13) { i0 = 1; i1 = 4; i2 = 7; i3 = 10; }
    else            { i0 = 1; i1 = 3; i2 = 5; i3 = 7;  }

    const float* w  = (const float*)d_in[0];
    const int4*  p0 = (const int4*) d_in[i0];
    const int4*  p1 = (const int4*) d_in[i1];
    const int4*  p2 = (const int4*) d_in[i2];
    const int4*  p3 = (const int4*) d_in[i3];

    int n_vars = in_sizes[0];
    int n0 = in_sizes[i0] / 4;
    int n1 = in_sizes[i1] / 4;
    int n2 = in_sizes[i2] / 4;
    int n3 = in_sizes[i3] / 4;   // == out_size

    // Host code runs only at capture time; query the real SM count so the
    // persistent grid is exactly BLKS_PER_SM blocks per SM.
    int nsm = 148;
    cudaDeviceGetAttribute(&nsm, cudaDevAttrMultiProcessorCount, 0);
    int nblk = BLKS_PER_SM * nsm;

    fused_kernel<<<nblk, NTHR>>>(w, p0, p1, p2, p3, (float*)d_out,
                                 n_vars, n0, n1, n2, n3);
}

// round 14
// speedup vs baseline: 1.9790x; 1.1183x over previous
#include <cuda_runtime.h>
#include <math_constants.h>

// ---------------------------------------------------------------------------
// 4-layer probabilistic circuit in log space, fixed fan-in 4, contiguous CSR.
// Best measured shape: one thread per output, one-shot grid (R5). This round
// folds the encode stage into layer 0 (on-the-fly log1mexp decode) removing
// one kernel + 16MB of x-array store traffic.
// ---------------------------------------------------------------------------

#define N0_MAX 4000000
#define N1_MAX 2000000
#define N2_MAX 1000000

__device__ float g_b0[N0_MAX];   // layer0 out, 16 MB
__device__ float g_b1[N1_MAX];   // layer1 out,  8 MB
__device__ float g_b2[N2_MAX];   // layer2 out,  4 MB

#define NTHR 256

// log1mexp(v) = log(1 - exp(v)) for v < 0, numerically accurate (matches ref)
__device__ __forceinline__ float log1mexp(float v)
{
    if (v > -0.69314718056f) {
        return __logf(-expm1f(v));
    } else {
        return log1pf(-__expf(v));
    }
}

// Decode one virtual x-array element on the fly:
//   x[0] = -inf, x[1] = 0, x[2+2i] = w[i], x[3+2i] = log1mexp(w[i])
__device__ __forceinline__ float fetch_encoded(const float* __restrict__ w, int p)
{
    int idx = (p >= 2) ? ((p - 2) >> 1) : 0;   // clamp keeps load in-bounds
    float v = __ldcg(w + idx);
    if (p & 1) v = log1mexp(v);                // odd slot -> negated literal
    if (p < 2) v = (p == 0) ? -CUDART_INF_F : 0.0f;
    return v;
}

// ---------------------------------------------------------------------------
// Layer 0: product node (sum of 4 logs), gathering straight from w with
// on-the-fly encode. One thread per output (R5 shape).
// ---------------------------------------------------------------------------
__global__ void sum0_kernel(const float* __restrict__ w,
                            const int4*  __restrict__ ptrs,
                            float*       __restrict__ out, int n)
{
    int j = blockIdx.x * blockDim.x + threadIdx.x;
    if (j >= n) return;
    int4 p = __ldg(ptrs + j);
    float a = fetch_encoded(w, p.x);
    float b = fetch_encoded(w, p.y);
    float c = fetch_encoded(w, p.z);
    float d = fetch_encoded(w, p.w);
    out[j] = (a + b) + (c + d);
}

// ---------------------------------------------------------------------------
// Product layer (log semiring): out[j] = sum of 4 gathered values.
// ---------------------------------------------------------------------------
__global__ void sum_kernel(const float* __restrict__ x,
                           const int4*  __restrict__ ptrs,
                           float*       __restrict__ out, int n)
{
    int j = blockIdx.x * blockDim.x + threadIdx.x;
    if (j >= n) return;
    int4 p = __ldg(ptrs + j);
    float a = __ldcg(x + p.x);
    float b = __ldcg(x + p.y);
    float c = __ldcg(x + p.z);
    float d = __ldcg(x + p.w);
    out[j] = (a + b) + (c + d);
}

// ---------------------------------------------------------------------------
// Sum layer (log semiring): stable 4-way log-sum-exp + 1e-15.
// m == -inf => all four -inf => -inf (matches reference nan_to_num path).
// ---------------------------------------------------------------------------
__global__ void lse_kernel(const float* __restrict__ x,
                           const int4*  __restrict__ ptrs,
                           float*       __restrict__ out, int n)
{
    int j = blockIdx.x * blockDim.x + threadIdx.x;
    if (j >= n) return;
    int4 p = __ldg(ptrs + j);
    float a = __ldcg(x + p.x);
    float b = __ldcg(x + p.y);
    float c = __ldcg(x + p.z);
    float d = __ldcg(x + p.w);
    float m = fmaxf(fmaxf(a, b), fmaxf(c, d));
    float r;
    if (m == -CUDART_INF_F) {
        r = -CUDART_INF_F;
    } else {
        float s = __expf(a - m) + __expf(b - m) + __expf(c - m) + __expf(d - m) + 1e-15f;
        r = __logf(s) + m;
    }
    out[j] = r;
}

extern "C" void kernel_launch(void* const* d_in, const int* in_sizes, int n_in,
                              void* d_out, int out_size)
{
    // metadata order (setup_inputs dict order):
    //   0:weights 1:ptrs0 2:csr0 3:n0 4:ptrs1 5:csr1 6:n1
    //   7:ptrs2 8:csr2 9:n2 10:ptrs3 11:csr3 12:n3
    // Fallback if scalars are not passed: 1:ptrs0 3:ptrs1 5:ptrs2 7:ptrs3
    int i0, i1, i2, i3;
    if (n_in >= 13) { i0 = 1; i1 = 4; i2 = 7; i3 = 10; }
    else            { i0 = 1; i1 = 3; i2 = 5; i3 = 7;  }

    const float* w  = (const float*)d_in[0];
    const int4*  p0 = (const int4*) d_in[i0];
    const int4*  p1 = (const int4*) d_in[i1];
    const int4*  p2 = (const int4*) d_in[i2];
    const int4*  p3 = (const int4*) d_in[i3];

    int n0 = in_sizes[i0] / 4;
    int n1 = in_sizes[i1] / 4;
    int n2 = in_sizes[i2] / 4;
    int n3 = in_sizes[i3] / 4;   // == out_size

    float *b0, *b1, *b2;
    cudaGetSymbolAddress((void**)&b0, g_b0);
    cudaGetSymbolAddress((void**)&b1, g_b1);
    cudaGetSymbolAddress((void**)&b2, g_b2);

    const int T = NTHR;
    sum0_kernel<<<(n0 + T - 1) / T, T>>>(w,  p0, b0, n0);
    lse_kernel <<<(n1 + T - 1) / T, T>>>(b0, p1, b1, n1);
    sum_kernel <<<(n2 + T - 1) / T, T>>>(b1, p2, b2, n2);
    lse_kernel <<<(n3 + T - 1) / T, T>>>(b2, p3, (float*)d_out, n3);
}

// round 15
// speedup vs baseline: 2.0082x; 1.0147x over previous
#include <cuda_runtime.h>
#include <math_constants.h>

// ---------------------------------------------------------------------------
// 4-layer probabilistic circuit in log space, fan-in 4, contiguous CSR.
// R14 shape (one thread per output, encode fused into layer 0) + PDL:
// each kernel prefetches its coalesced ptr quad, signals dependents early,
// then waits for the predecessor grid before gathering. This overlaps the
// next layer's DRAM ptr fetch with the current layer's tail drain.
// ---------------------------------------------------------------------------

#define N0_MAX 4000000
#define N1_MAX 2000000
#define N2_MAX 1000000

__device__ float g_b0[N0_MAX];   // layer0 out, 16 MB
__device__ float g_b1[N1_MAX];   // layer1 out,  8 MB
__device__ float g_b2[N2_MAX];   // layer2 out,  4 MB

#define NTHR 256

__device__ __forceinline__ void pdl_launch_dependents() {
    asm volatile("griddepcontrol.launch_dependents;");
}
__device__ __forceinline__ void pdl_wait() {
    asm volatile("griddepcontrol.wait;" ::: "memory");
}

// log1mexp(v) = log(1 - exp(v)) for v < 0 (numerically matches reference)
__device__ __forceinline__ float log1mexp(float v)
{
    if (v > -0.69314718056f) {
        return __logf(-expm1f(v));
    } else {
        return log1pf(-__expf(v));
    }
}

// Decode one virtual encoded element on the fly:
//   x[0] = -inf, x[1] = 0, x[2+2i] = w[i], x[3+2i] = log1mexp(w[i])
__device__ __forceinline__ float fetch_encoded(const float* __restrict__ w, int p)
{
    int idx = (p >= 2) ? ((p - 2) >> 1) : 0;   // clamp keeps load in-bounds
    float v = __ldcg(w + idx);
    if (p & 1) v = log1mexp(v);                // odd slot -> negated literal
    if (p < 2) v = (p == 0) ? -CUDART_INF_F : 0.0f;
    return v;
}

// ---------------------------------------------------------------------------
// Layer 0: product node, gathering straight from w with on-the-fly encode.
// No predecessor -> no pdl_wait needed before gathers (w is a graph input).
// ---------------------------------------------------------------------------
__global__ void sum0_kernel(const float* __restrict__ w,
                            const int4*  __restrict__ ptrs,
                            float*       __restrict__ out, int n)
{
    int j = blockIdx.x * blockDim.x + threadIdx.x;
    pdl_launch_dependents();            // let lse1 start prefetching its ptrs
    if (j >= n) return;
    int4 p = __ldcs(ptrs + j);          // streaming: evict-first in L2
    float a = fetch_encoded(w, p.x);
    float b = fetch_encoded(w, p.y);
    float c = fetch_encoded(w, p.z);
    float d = fetch_encoded(w, p.w);
    out[j] = (a + b) + (c + d);
}

// ---------------------------------------------------------------------------
// Product layer: out[j] = sum of 4 gathered log-values.
// Ptr quad is prefetched BEFORE pdl_wait so the DRAM fetch overlaps the
// predecessor's tail; gathers happen only after the predecessor completes.
// ---------------------------------------------------------------------------
__global__ void sum_kernel(const float* __restrict__ x,
                           const int4*  __restrict__ ptrs,
                           float*       __restrict__ out, int n)
{
    int j = blockIdx.x * blockDim.x + threadIdx.x;
    pdl_launch_dependents();
    int4 p;
    if (j < n) p = __ldcs(ptrs + j);    // issue prefetch (independent of pred)
    pdl_wait();                         // predecessor results now visible
    if (j >= n) return;
    float a = __ldcg(x + p.x);
    float b = __ldcg(x + p.y);
    float c = __ldcg(x + p.z);
    float d = __ldcg(x + p.w);
    out[j] = (a + b) + (c + d);
}

// ---------------------------------------------------------------------------
// Sum layer: stable 4-way log-sum-exp + 1e-15.
// m == -inf => all four -inf => -inf (matches reference nan_to_num path).
// ---------------------------------------------------------------------------
__global__ void lse_kernel(const float* __restrict__ x,
                           const int4*  __restrict__ ptrs,
                           float*       __restrict__ out, int n)
{
    int j = blockIdx.x * blockDim.x + threadIdx.x;
    pdl_launch_dependents();
    int4 p;
    if (j < n) p = __ldcs(ptrs + j);
    pdl_wait();
    if (j >= n) return;
    float a = __ldcg(x + p.x);
    float b = __ldcg(x + p.y);
    float c = __ldcg(x + p.z);
    float d = __ldcg(x + p.w);
    float m = fmaxf(fmaxf(a, b), fmaxf(c, d));
    float r;
    if (m == -CUDART_INF_F) {
        r = -CUDART_INF_F;
    } else {
        float s = __expf(a - m) + __expf(b - m) + __expf(c - m) + __expf(d - m) + 1e-15f;
        r = __logf(s) + m;
    }
    out[j] = r;
}

// ---------------------------------------------------------------------------
// Host side: launch with the ProgrammaticStreamSerialization attribute so
// each kernel may begin (and prefetch) before its predecessor fully drains.
// ---------------------------------------------------------------------------
template <typename... Args>
static void launch_pdl(void (*kern)(Args...), int blocks, Args... args)
{
    cudaLaunchConfig_t cfg = {};
    cfg.gridDim  = dim3(blocks);
    cfg.blockDim = dim3(NTHR);
    cfg.stream   = 0;                   // legacy default stream (capture stream)
    cudaLaunchAttribute at[1];
    at[0].id = cudaLaunchAttributeProgrammaticStreamSerialization;
    at[0].val.programmaticStreamSerializationAllowed = 1;
    cfg.attrs    = at;
    cfg.numAttrs = 1;
    cudaLaunchKernelEx(&cfg, kern, args...);
}

extern "C" void kernel_launch(void* const* d_in, const int* in_sizes, int n_in,
                              void* d_out, int out_size)
{
    // metadata order (setup_inputs dict order):
    //   0:weights 1:ptrs0 2:csr0 3:n0 4:ptrs1 5:csr1 6:n1
    //   7:ptrs2 8:csr2 9:n2 10:ptrs3 11:csr3 12:n3
    // Fallback if scalars are not passed: 1:ptrs0 3:ptrs1 5:ptrs2 7:ptrs3
    int i0, i1, i2, i3;
    if (n_in >= 13) { i0 = 1; i1 = 4; i2 = 7; i3 = 10; }
    else            { i0 = 1; i1 = 3; i2 = 5; i3 = 7;  }

    const float* w  = (const float*)d_in[0];
    const int4*  p0 = (const int4*) d_in[i0];
    const int4*  p1 = (const int4*) d_in[i1];
    const int4*  p2 = (const int4*) d_in[i2];
    const int4*  p3 = (const int4*) d_in[i3];

    int n0 = in_sizes[i0] / 4;
    int n1 = in_sizes[i1] / 4;
    int n2 = in_sizes[i2] / 4;
    int n3 = in_sizes[i3] / 4;   // == out_size

    float *b0, *b1, *b2;
    cudaGetSymbolAddress((void**)&b0, g_b0);
    cudaGetSymbolAddress((void**)&b1, g_b1);
    cudaGetSymbolAddress((void**)&b2, g_b2);

    const int T = NTHR;
    launch_pdl(sum0_kernel, (n0 + T - 1) / T, w,  p0, b0, n0);
    launch_pdl(lse_kernel,  (n1 + T - 1) / T, (const float*)b0, p1, b1, n1);
    launch_pdl(sum_kernel,  (n2 + T - 1) / T, (const float*)b1, p2, b2, n2);
    launch_pdl(lse_kernel,  (n3 + T - 1) / T, (const float*)b2, p3, (float*)d_out, n3);
}

// round 17
// speedup vs baseline: 2.0464x; 1.0190x over previous
#include <cuda_runtime.h>
#include <math_constants.h>

// ---------------------------------------------------------------------------
// 4-layer probabilistic circuit in log space, fan-in 4, contiguous CSR.
// R15 winner (encode fused into layer 0 + PDL overlap) + U=2 per-thread
// batching to double in-flight gathers on the latency-bound small layers.
// ---------------------------------------------------------------------------

#define N0_MAX 4000000
#define N1_MAX 2000000
#define N2_MAX 1000000

__device__ float g_b0[N0_MAX];   // layer0 out, 16 MB
__device__ float g_b1[N1_MAX];   // layer1 out,  8 MB
__device__ float g_b2[N2_MAX];   // layer2 out,  4 MB

#define NTHR 256
#define UB   2                   // outputs per thread

__device__ __forceinline__ void pdl_launch_dependents() {
    asm volatile("griddepcontrol.launch_dependents;");
}
__device__ __forceinline__ void pdl_wait() {
    asm volatile("griddepcontrol.wait;" ::: "memory");
}

// log1mexp(v) = log(1 - exp(v)) for v < 0 (numerically matches reference)
__device__ __forceinline__ float log1mexp(float v)
{
    if (v > -0.69314718056f) {
        return __logf(-expm1f(v));
    } else {
        return log1pf(-__expf(v));
    }
}

// Decode one virtual encoded element on the fly:
//   x[0] = -inf, x[1] = 0, x[2+2i] = w[i], x[3+2i] = log1mexp(w[i])
__device__ __forceinline__ float decode(float v, int p)
{
    if (p & 1) v = log1mexp(v);                // odd slot -> negated literal
    if (p < 2) v = (p == 0) ? -CUDART_INF_F : 0.0f;
    return v;
}

// ---------------------------------------------------------------------------
// Layer 0: product node, gathering straight from w with on-the-fly encode.
// U=2 outputs/thread; all 8 gathers issued before any decode math.
// ---------------------------------------------------------------------------
__global__ void sum0_kernel(const float* __restrict__ w,
                            const int4*  __restrict__ ptrs,
                            float*       __restrict__ out, int n)
{
    const int S = gridDim.x * blockDim.x;
    const int j0 = blockIdx.x * blockDim.x + threadIdx.x;
    pdl_launch_dependents();

    int4 p[UB]; bool act[UB];
    #pragma unroll
    for (int k = 0; k < UB; k++) {
        int j = j0 + k * S;
        act[k] = (j < n);
        if (act[k]) p[k] = __ldcs(ptrs + j);
    }
    float va[UB], vb[UB], vc[UB], vd[UB];
    #pragma unroll
    for (int k = 0; k < UB; k++) {
        if (act[k]) {
            va[k] = __ldcg(w + ((p[k].x >= 2) ? ((p[k].x - 2) >> 1) : 0));
            vb[k] = __ldcg(w + ((p[k].y >= 2) ? ((p[k].y - 2) >> 1) : 0));
            vc[k] = __ldcg(w + ((p[k].z >= 2) ? ((p[k].z - 2) >> 1) : 0));
            vd[k] = __ldcg(w + ((p[k].w >= 2) ? ((p[k].w - 2) >> 1) : 0));
        }
    }
    #pragma unroll
    for (int k = 0; k < UB; k++) {
        if (act[k]) {
            float a = decode(va[k], p[k].x);
            float b = decode(vb[k], p[k].y);
            float c = decode(vc[k], p[k].z);
            float d = decode(vd[k], p[k].w);
            out[j0 + k * S] = (a + b) + (c + d);
        }
    }
}

// ---------------------------------------------------------------------------
// Product layer: out[j] = sum of 4 gathered log-values, U=2 outputs/thread.
// Ptr quads prefetched BEFORE pdl_wait (independent of predecessor output).
// ---------------------------------------------------------------------------
__global__ void sum_kernel(const float* __restrict__ x,
                           const int4*  __restrict__ ptrs,
                           float*       __restrict__ out, int n)
{
    const int S = gridDim.x * blockDim.x;
    const int j0 = blockIdx.x * blockDim.x + threadIdx.x;
    pdl_launch_dependents();

    int4 p[UB]; bool act[UB];
    #pragma unroll
    for (int k = 0; k < UB; k++) {
        int j = j0 + k * S;
        act[k] = (j < n);
        if (act[k]) p[k] = __ldcs(ptrs + j);
    }
    pdl_wait();                          // predecessor results now visible
    float va[UB], vb[UB], vc[UB], vd[UB];
    #pragma unroll
    for (int k = 0; k < UB; k++) {
        if (act[k]) {
            va[k] = __ldcg(x + p[k].x);
            vb[k] = __ldcg(x + p[k].y);
            vc[k] = __ldcg(x + p[k].z);
            vd[k] = __ldcg(x + p[k].w);
        }
    }
    #pragma unroll
    for (int k = 0; k < UB; k++) {
        if (act[k]) out[j0 + k * S] = (va[k] + vb[k]) + (vc[k] + vd[k]);
    }
}

// ---------------------------------------------------------------------------
// Sum layer: stable 4-way log-sum-exp + 1e-15, U=2 outputs/thread.
// m == -inf => all four -inf => -inf (matches reference nan_to_num path).
// ---------------------------------------------------------------------------
__global__ void lse_kernel(const float* __restrict__ x,
                           const int4*  __restrict__ ptrs,
                           float*       __restrict__ out, int n)
{
    const int S = gridDim.x * blockDim.x;
    const int j0 = blockIdx.x * blockDim.x + threadIdx.x;
    pdl_launch_dependents();

    int4 p[UB]; bool act[UB];
    #pragma unroll
    for (int k = 0; k < UB; k++) {
        int j = j0 + k * S;
        act[k] = (j < n);
        if (act[k]) p[k] = __ldcs(ptrs + j);
    }
    pdl_wait();
    float va[UB], vb[UB], vc[UB], vd[UB];
    #pragma unroll
    for (int k = 0; k < UB; k++) {
        if (act[k]) {
            va[k] = __ldcg(x + p[k].x);
            vb[k] = __ldcg(x + p[k].y);
            vc[k] = __ldcg(x + p[k].z);
            vd[k] = __ldcg(x + p[k].w);
        }
    }
    #pragma unroll
    for (int k = 0; k < UB; k++) {
        if (act[k]) {
            float m = fmaxf(fmaxf(va[k], vb[k]), fmaxf(vc[k], vd[k]));
            float r;
            if (m == -CUDART_INF_F) {
                r = -CUDART_INF_F;
            } else {
                float s = __expf(va[k] - m) + __expf(vb[k] - m)
                        + __expf(vc[k] - m) + __expf(vd[k] - m) + 1e-15f;
                r = __logf(s) + m;
            }
            out[j0 + k * S] = r;
        }
    }
}

// ---------------------------------------------------------------------------
// Host side: PDL launches (ProgrammaticStreamSerialization) on the capture
// stream so each kernel overlaps its ptr prefetch with predecessor drain.
// ---------------------------------------------------------------------------
template <typename... Args>
static void launch_pdl(void (*kern)(Args...), int blocks, Args... args)
{
    cudaLaunchConfig_t cfg = {};
    cfg.gridDim  = dim3(blocks);
    cfg.blockDim = dim3(NTHR);
    cfg.stream   = 0;
    cudaLaunchAttribute at[1];
    at[0].id = cudaLaunchAttributeProgrammaticStreamSerialization;
    at[0].val.programmaticStreamSerializationAllowed = 1;
    cfg.attrs    = at;
    cfg.numAttrs = 1;
    cudaLaunchKernelEx(&cfg, kern, args...);
}

extern "C" void kernel_launch(void* const* d_in, const int* in_sizes, int n_in,
                              void* d_out, int out_size)
{
    // metadata order (setup_inputs dict order):
    //   0:weights 1:ptrs0 2:csr0 3:n0 4:ptrs1 5:csr1 6:n1
    //   7:ptrs2 8:csr2 9:n2 10:ptrs3 11:csr3 12:n3
    // Fallback if scalars are not passed: 1:ptrs0 3:ptrs1 5:ptrs2 7:ptrs3
    int i0, i1, i2, i3;
    if (n_in >= 13) { i0 = 1; i1 = 4; i2 = 7; i3 = 10; }
    else            { i0 = 1; i1 = 3; i2 = 5; i3 = 7;  }

    const float* w  = (const float*)d_in[0];
    const int4*  p0 = (const int4*) d_in[i0];
    const int4*  p1 = (const int4*) d_in[i1];
    const int4*  p2 = (const int4*) d_in[i2];
    const int4*  p3 = (const int4*) d_in[i3];

    int n0 = in_sizes[i0] / 4;
    int n1 = in_sizes[i1] / 4;
    int n2 = in_sizes[i2] / 4;
    int n3 = in_sizes[i3] / 4;   // == out_size

    float *b0, *b1, *b2;
    cudaGetSymbolAddress((void**)&b0, g_b0);
    cudaGetSymbolAddress((void**)&b1, g_b1);
    cudaGetSymbolAddress((void**)&b2, g_b2);

    const int TU = NTHR * UB;
    launch_pdl(sum0_kernel, (n0 + TU - 1) / TU, w,  p0, b0, n0);
    launch_pdl(lse_kernel,  (n1 + TU - 1) / TU, (const float*)b0, p1, b1, n1);
    launch_pdl(sum_kernel,  (n2 + TU - 1) / TU, (const float*)b1, p2, b2, n2);
    launch_pdl(lse_kernel,  (n3 + TU - 1) / TU, (const float*)b2, p3, (float*)d_out, n3);
}